// round 5
// baseline (speedup 1.0000x reference)
#include <cuda_runtime.h>
#include <math.h>

#define Bb   4
#define Ls   1024
#define Hh   768
#define NHh  12
#define NEe  30
#define Mm   6
#define Pp   600
#define EMBe 768
#define NCc  97
#define K2H  1536           // 2*H
#define QQ   12288          // EMB*BS
#define BP   (Bb*Pp)        // 2400
#define BE   (Bb*NEe)       // 120
#define EKC  3              // K-chunks for E gemm
#define BLKS 16             // bilinear K-split

// ---------------- scratch ----------------
__device__ float g_e_emb[BE*Hh];
__device__ float g_e_att[BE*NHh*Ls];
__device__ float g_ht  [BP*Ls];
__device__ float g_rsp [2*BP*Hh];          // rs partials [kc][b][p][h]
__device__ float g_R   [2*BP*Hh];          // [side][m][e]
__device__ float g_Ep  [EKC*2*BE*Hh];
__device__ float g_hs  [BP*EMBe];
__device__ float g_ts  [BP*EMBe];
__device__ float g_Wcp [2*NCc*QQ];         // Wc partials
__device__ float g_WcT [QQ*128];           // transposed+merged, c padded to 128
__device__ float g_blp [BLKS*BP*128];      // bilinear partials

// ---------------- kernel 1: entity pooling ----------------
__global__ void pool_kernel(const float* __restrict__ seq,
                            const float* __restrict__ att,
                            const float* __restrict__ mmask,
                            const int*   __restrict__ midx)
{
    int be = blockIdx.x;
    int b = be / NEe;
    __shared__ int   idx[Mm];
    __shared__ float msk[Mm];
    if (threadIdx.x < Mm) {
        idx[threadIdx.x] = midx[be*Mm + threadIdx.x];
        msk[threadIdx.x] = mmask[be*Mm + threadIdx.x];
    }
    __syncthreads();
    float cnt = 0.f;
    #pragma unroll
    for (int m = 0; m < Mm; m++) cnt += msk[m];
    cnt = fmaxf(cnt, 1.0f);
    float invc = 1.0f / cnt;

    for (int h = threadIdx.x; h < Hh; h += blockDim.x) {
        float v[Mm]; float mx = -1e30f;
        #pragma unroll
        for (int m = 0; m < Mm; m++) {
            float x = seq[((long)b*Ls + idx[m])*Hh + h];
            x = (msk[m] > 0.f) ? x : -1e30f;
            v[m] = x; mx = fmaxf(mx, x);
        }
        float s = 0.f;
        #pragma unroll
        for (int m = 0; m < Mm; m++) s += expf(v[m] - mx);
        g_e_emb[(long)be*Hh + h] = mx + logf(s);
    }
    // attention mean, float4 over l
    for (int t = threadIdx.x; t < NHh*(Ls/4); t += blockDim.x) {
        int nh = t >> 8, lq = (t & 255)*4;
        float4 s4 = make_float4(0.f,0.f,0.f,0.f);
        #pragma unroll
        for (int m = 0; m < Mm; m++) {
            float4 a = *(const float4*)&att[(((long)b*NHh + nh)*Ls + idx[m])*Ls + lq];
            float w = msk[m];
            s4.x += a.x*w; s4.y += a.y*w; s4.z += a.z*w; s4.w += a.w*w;
        }
        s4.x *= invc; s4.y *= invc; s4.z *= invc; s4.w *= invc;
        *(float4*)&g_e_att[((long)be*NHh + nh)*Ls + lq] = s4;
    }
}

// ---------------- kernel 2: pairwise attention mix (float4) ----------------
__global__ void htatt_kernel(const int* __restrict__ hts)
{
    int bp = blockIdx.x;
    int b = bp / Pp;
    int he = hts[bp*2 + 0];
    int te = hts[bp*2 + 1];
    const float* ha = &g_e_att[((long)(b*NEe + he))*NHh*Ls];
    const float* ta = &g_e_att[((long)(b*NEe + te))*NHh*Ls];
    __shared__ float sv[Ls];
    __shared__ float red[256];
    int lq = threadIdx.x * 4;            // 256 threads x 4 = 1024
    float4 s4 = make_float4(0.f,0.f,0.f,0.f);
    #pragma unroll
    for (int nh = 0; nh < NHh; nh++) {
        float4 a = *(const float4*)&ha[nh*Ls + lq];
        float4 t = *(const float4*)&ta[nh*Ls + lq];
        s4.x += a.x*t.x; s4.y += a.y*t.y; s4.z += a.z*t.z; s4.w += a.w*t.w;
    }
    const float inh = 1.0f / NHh;
    s4.x *= inh; s4.y *= inh; s4.z *= inh; s4.w *= inh;
    *(float4*)&sv[lq] = s4;
    red[threadIdx.x] = s4.x + s4.y + s4.z + s4.w;
    for (int o = 128; o > 0; o >>= 1) {
        __syncthreads();
        if (threadIdx.x < o) red[threadIdx.x] += red[threadIdx.x + o];
    }
    __syncthreads();
    float inv = 1.0f / (red[0] + 1e-30f);
    float4 v = *(const float4*)&sv[lq];
    v.x *= inv; v.y *= inv; v.z *= inv; v.w *= inv;
    *(float4*)&g_ht[(long)bp*Ls + lq] = v;
}

// ---------------- 128x128 NN GEMM, 8x8 micro, double-buffered, K-split -------
// z = bz*ksplit + kc.  Partial C layout: [kc][bz][M][N] (stride sC per (kc,bz)).
__global__ __launch_bounds__(256,2) void gemm_nn128(
    const float* __restrict__ A, const float* __restrict__ B, float* __restrict__ C,
    int M, int N, int K, long sA, long sB, long sC, int ksplit)
{
    __shared__ float As[2][8][132];
    __shared__ float Bs[2][8][132];
    int z = blockIdx.z;
    int kc = z % ksplit;
    int bz = z / ksplit;
    int nbz = gridDim.z / ksplit;
    int klen = K / ksplit;
    int kbeg = kc * klen, kend = kbeg + klen;
    const float* Ab = A + (long)bz*sA;
    const float* Bp = B + (long)bz*sB;
    float*       Cb = C + ((long)kc*nbz + bz)*sC;
    int m0 = blockIdx.x*128, n0 = blockIdx.y*128;
    int tid = threadIdx.x;

    int ar = tid >> 1, akq = (tid & 1)*4;
    int am = m0 + ar; if (am > M-1) am = M-1;
    int bkr = tid >> 5, bnq = (tid & 31)*4;
    const float* aptr = Ab + (long)am*K + kbeg + akq;
    const float* bptr = Bp + (long)(kbeg + bkr)*N + n0 + bnq;

    float4 av = *(const float4*)aptr;
    float4 bv = *(const float4*)bptr;

    int tm = tid & 15, tn = tid >> 4;
    float acc[8][8] = {};
    int buf = 0;
    As[0][akq+0][ar] = av.x; As[0][akq+1][ar] = av.y;
    As[0][akq+2][ar] = av.z; As[0][akq+3][ar] = av.w;
    *(float4*)&Bs[0][bkr][bnq] = bv;
    __syncthreads();

    for (int k0 = kbeg; k0 < kend; k0 += 8) {
        bool next = (k0 + 8 < kend);
        if (next) {
            aptr += 8; bptr += (long)8*N;
            av = *(const float4*)aptr;
            bv = *(const float4*)bptr;
        }
        #pragma unroll
        for (int kk = 0; kk < 8; kk++) {
            float a[8], b[8];
            *(float4*)&a[0] = *(const float4*)&As[buf][kk][tm*8];
            *(float4*)&a[4] = *(const float4*)&As[buf][kk][tm*8+4];
            *(float4*)&b[0] = *(const float4*)&Bs[buf][kk][tn*8];
            *(float4*)&b[4] = *(const float4*)&Bs[buf][kk][tn*8+4];
            #pragma unroll
            for (int i = 0; i < 8; i++)
                #pragma unroll
                for (int j = 0; j < 8; j++)
                    acc[i][j] += a[i]*b[j];
        }
        if (next) {
            int nb = buf ^ 1;
            As[nb][akq+0][ar] = av.x; As[nb][akq+1][ar] = av.y;
            As[nb][akq+2][ar] = av.z; As[nb][akq+3][ar] = av.w;
            *(float4*)&Bs[nb][bkr][bnq] = bv;
            __syncthreads();
            buf = nb;
        }
    }
    #pragma unroll
    for (int i = 0; i < 8; i++) {
        int m = m0 + tm*8 + i;
        if (m >= M) continue;
        float4 o0 = make_float4(acc[i][0], acc[i][1], acc[i][2], acc[i][3]);
        float4 o1 = make_float4(acc[i][4], acc[i][5], acc[i][6], acc[i][7]);
        *(float4*)&Cb[(long)m*N + n0 + tn*8    ] = o0;
        *(float4*)&Cb[(long)m*N + n0 + tn*8 + 4] = o1;
    }
}

// ---------------- Wc merge + transpose: g_WcT[q][c] = p0[c][q]+p1[c][q] ------
__global__ void wct_kernel()
{
    __shared__ float sm[32][33];
    int q0 = blockIdx.x * 32;
    int c0 = blockIdx.y * 32;
    int tx = threadIdx.x, ty = threadIdx.y;    // (32, 8)
    #pragma unroll
    for (int u = 0; u < 4; u++) {
        int c = c0 + ty + u*8;
        float v = 0.f;
        if (c < NCc) {
            long o = (long)c*QQ + q0 + tx;
            v = g_Wcp[o] + g_Wcp[(long)NCc*QQ + o];
        }
        sm[ty + u*8][tx] = v;
    }
    __syncthreads();
    #pragma unroll
    for (int u = 0; u < 4; u++) {
        int q = q0 + ty + u*8;
        g_WcT[(long)q*128 + c0 + tx] = sm[tx][ty + u*8];
    }
}

// ---------------- R GEMM (NT): g_R[side] = (rsp0+rsp1) @ W[:,768:]^T ---------
__global__ __launch_bounds__(256,2) void r_gemm(
    const float* __restrict__ headW, const float* __restrict__ tailW)
{
    __shared__ float As[2][8][132];
    __shared__ float Bs[2][8][132];
    int side = blockIdx.z;
    const float* W = side ? tailW : headW;
    float* Cb = g_R + (long)side*BP*Hh;
    int m0 = blockIdx.x*128, n0 = blockIdx.y*128;
    int tid = threadIdx.x;

    int ar = tid >> 1, akq = (tid & 1)*4;
    int am = m0 + ar; if (am > BP-1) am = BP-1;
    int bn = tid >> 1, bkq = (tid & 1)*4;
    const float* aptr = g_rsp + (long)am*Hh + akq;          // partial 0
    const float* bptr = W + (long)(n0 + bn)*K2H + Hh + bkq;
    const long POFF = (long)BP*Hh;                          // partial 1 offset

    float4 a0 = *(const float4*)aptr;
    float4 a1 = *(const float4*)(aptr + POFF);
    float4 bv = *(const float4*)bptr;
    float4 av = make_float4(a0.x+a1.x, a0.y+a1.y, a0.z+a1.z, a0.w+a1.w);

    int tm = tid & 15, tn = tid >> 4;
    float acc[8][8] = {};
    int buf = 0;
    As[0][akq+0][ar] = av.x; As[0][akq+1][ar] = av.y;
    As[0][akq+2][ar] = av.z; As[0][akq+3][ar] = av.w;
    Bs[0][bkq+0][bn] = bv.x; Bs[0][bkq+1][bn] = bv.y;
    Bs[0][bkq+2][bn] = bv.z; Bs[0][bkq+3][bn] = bv.w;
    __syncthreads();

    for (int k0 = 0; k0 < Hh; k0 += 8) {
        bool next = (k0 + 8 < Hh);
        if (next) {
            aptr += 8; bptr += 8;
            a0 = *(const float4*)aptr;
            a1 = *(const float4*)(aptr + POFF);
            bv = *(const float4*)bptr;
            av = make_float4(a0.x+a1.x, a0.y+a1.y, a0.z+a1.z, a0.w+a1.w);
        }
        #pragma unroll
        for (int kk = 0; kk < 8; kk++) {
            float a[8], b[8];
            *(float4*)&a[0] = *(const float4*)&As[buf][kk][tm*8];
            *(float4*)&a[4] = *(const float4*)&As[buf][kk][tm*8+4];
            *(float4*)&b[0] = *(const float4*)&Bs[buf][kk][tn*8];
            *(float4*)&b[4] = *(const float4*)&Bs[buf][kk][tn*8+4];
            #pragma unroll
            for (int i = 0; i < 8; i++)
                #pragma unroll
                for (int j = 0; j < 8; j++)
                    acc[i][j] += a[i]*b[j];
        }
        if (next) {
            int nb = buf ^ 1;
            As[nb][akq+0][ar] = av.x; As[nb][akq+1][ar] = av.y;
            As[nb][akq+2][ar] = av.z; As[nb][akq+3][ar] = av.w;
            Bs[nb][bkq+0][bn] = bv.x; Bs[nb][bkq+1][bn] = bv.y;
            Bs[nb][bkq+2][bn] = bv.z; Bs[nb][bkq+3][bn] = bv.w;
            __syncthreads();
            buf = nb;
        }
    }
    #pragma unroll
    for (int i = 0; i < 8; i++) {
        int m = m0 + tm*8 + i;
        if (m >= BP) continue;
        float4 o0 = make_float4(acc[i][0], acc[i][1], acc[i][2], acc[i][3]);
        float4 o1 = make_float4(acc[i][4], acc[i][5], acc[i][6], acc[i][7]);
        *(float4*)&Cb[(long)m*Hh + n0 + tn*8    ] = o0;
        *(float4*)&Cb[(long)m*Hh + n0 + tn*8 + 4] = o1;
    }
}

// ---------------- E GEMM (NT, K-chunked, 64x64 tile) ----------------
__global__ __launch_bounds__(256) void e_gemm(
    const float* __restrict__ headW, const float* __restrict__ tailW)
{
    __shared__ float As[16][65];
    __shared__ float Bs[16][65];
    int z = blockIdx.z;
    int side = z & 1, kc = z >> 1;
    const float* W = side ? tailW : headW;
    float* Cb = g_Ep + (long)(kc*2 + side)*BE*Hh;
    int m0 = blockIdx.x*64, n0 = blockIdx.y*64;
    int tid = threadIdx.x;
    int tm = tid & 15, tn = tid >> 4;
    float acc[4][4] = {};
    int kbeg = kc*256, kend = kbeg + 256;
    for (int k0 = kbeg; k0 < kend; k0 += 16) {
        #pragma unroll
        for (int i = 0; i < 4; i++) {
            int idx = tid + i*256;
            int m = idx >> 4, k = idx & 15;
            int mg = m0 + m; if (mg > BE-1) mg = BE-1;
            As[k][m] = g_e_emb[(long)mg*Hh + k0 + k];
        }
        #pragma unroll
        for (int i = 0; i < 4; i++) {
            int idx = tid + i*256;
            int e = idx >> 4, k = idx & 15;
            Bs[k][e] = W[(long)(n0 + e)*K2H + k0 + k];
        }
        __syncthreads();
        #pragma unroll
        for (int kk = 0; kk < 16; kk++) {
            float a[4], bb[4];
            #pragma unroll
            for (int i = 0; i < 4; i++) a[i]  = As[kk][tm + 16*i];
            #pragma unroll
            for (int j = 0; j < 4; j++) bb[j] = Bs[kk][tn + 16*j];
            #pragma unroll
            for (int i = 0; i < 4; i++)
                #pragma unroll
                for (int j = 0; j < 4; j++)
                    acc[i][j] += a[i]*bb[j];
        }
        __syncthreads();
    }
    #pragma unroll
    for (int i = 0; i < 4; i++) {
        int m = m0 + tm + 16*i;
        if (m >= BE) continue;
        #pragma unroll
        for (int j = 0; j < 4; j++)
            Cb[(long)m*Hh + n0 + tn + 16*j] = acc[i][j];
    }
}

// ---------------- fused gather + add + tanh ----------------
__global__ void fuse_tanh(const float* __restrict__ headb,
                          const float* __restrict__ tailb,
                          const int*   __restrict__ hts)
{
    int m = blockIdx.x, side = blockIdx.y;
    int b = m / Pp;
    int ent = hts[m*2 + side];
    int er = b*NEe + ent;
    const float* Rr   = g_R + ((long)side*BP + m)*Hh;
    const float* bias = side ? tailb : headb;
    float* outp = (side ? g_ts : g_hs) + (long)m*EMBe;
    const float* e0 = g_Ep + (long)(0*2 + side)*BE*Hh + (long)er*Hh;
    const float* e1 = g_Ep + (long)(1*2 + side)*BE*Hh + (long)er*Hh;
    const float* e2 = g_Ep + (long)(2*2 + side)*BE*Hh + (long)er*Hh;
    int e = threadIdx.x * 4;
    float4 r  = *(const float4*)&Rr[e];
    float4 p0 = *(const float4*)&e0[e];
    float4 p1 = *(const float4*)&e1[e];
    float4 p2 = *(const float4*)&e2[e];
    float4 bi = *(const float4*)&bias[e];
    float4 o;
    o.x = tanhf(r.x + p0.x + p1.x + p2.x + bi.x);
    o.y = tanhf(r.y + p0.y + p1.y + p2.y + bi.y);
    o.z = tanhf(r.z + p0.z + p1.z + p2.z + bi.z);
    o.w = tanhf(r.w + p0.w + p1.w + p2.w + bi.w);
    *(float4*)&outp[e] = o;
}

// ---------------- bilinear as GEMM: A materialized, B = WcT -------------------
// A[m,q] = hs[m,16kb+i]*ts[m,16kb+j], q = 256kb+16i+j.  N=128 (c padded).
// grid (19, 1, BLKS); k range per block = QQ/BLKS = 768.
__global__ __launch_bounds__(256,2) void bilinear_gemm()
{
    __shared__ float As[2][8][132];
    __shared__ float Bs[2][8][132];
    int kc = blockIdx.z;
    int kbeg = kc * (QQ / BLKS), kend = kbeg + (QQ / BLKS);
    int m0 = blockIdx.x*128;
    int tid = threadIdx.x;

    int ar = tid >> 1, akq = (tid & 1)*4;
    int am = m0 + ar; if (am > BP-1) am = BP-1;
    int bkr = tid >> 5, bnq = (tid & 31)*4;
    const float* bptr = g_WcT + (long)(kbeg + bkr)*128 + bnq;

    // A materialize for q-tile starting at q0
    const float* hrow = g_hs + (long)am*EMBe;
    const float* trow = g_ts + (long)am*EMBe;
    int q0 = kbeg;
    int kb = q0 >> 8, iQ = (q0 >> 4) & 15, jb = q0 & 8;
    float4 t4 = *(const float4*)&trow[(kb<<4) + jb + akq];
    float  hv = hrow[(kb<<4) + iQ];
    float4 av = make_float4(hv*t4.x, hv*t4.y, hv*t4.z, hv*t4.w);
    float4 bv = *(const float4*)bptr;

    int tm = tid & 15, tn = tid >> 4;
    float acc[8][8] = {};
    int buf = 0;
    As[0][akq+0][ar] = av.x; As[0][akq+1][ar] = av.y;
    As[0][akq+2][ar] = av.z; As[0][akq+3][ar] = av.w;
    *(float4*)&Bs[0][bkr][bnq] = bv;
    __syncthreads();

    for (int k0 = kbeg; k0 < kend; k0 += 8) {
        bool next = (k0 + 8 < kend);
        if (next) {
            int q1 = k0 + 8;
            kb = q1 >> 8; iQ = (q1 >> 4) & 15; jb = q1 & 8;
            t4 = *(const float4*)&trow[(kb<<4) + jb + akq];
            hv = hrow[(kb<<4) + iQ];
            av = make_float4(hv*t4.x, hv*t4.y, hv*t4.z, hv*t4.w);
            bptr += 8*128;
            bv = *(const float4*)bptr;
        }
        #pragma unroll
        for (int kk = 0; kk < 8; kk++) {
            float a[8], b[8];
            *(float4*)&a[0] = *(const float4*)&As[buf][kk][tm*8];
            *(float4*)&a[4] = *(const float4*)&As[buf][kk][tm*8+4];
            *(float4*)&b[0] = *(const float4*)&Bs[buf][kk][tn*8];
            *(float4*)&b[4] = *(const float4*)&Bs[buf][kk][tn*8+4];
            #pragma unroll
            for (int i = 0; i < 8; i++)
                #pragma unroll
                for (int j = 0; j < 8; j++)
                    acc[i][j] += a[i]*b[j];
        }
        if (next) {
            int nb = buf ^ 1;
            As[nb][akq+0][ar] = av.x; As[nb][akq+1][ar] = av.y;
            As[nb][akq+2][ar] = av.z; As[nb][akq+3][ar] = av.w;
            *(float4*)&Bs[nb][bkr][bnq] = bv;
            __syncthreads();
            buf = nb;
        }
    }
    float* Cb = g_blp + (long)kc*BP*128;
    #pragma unroll
    for (int i = 0; i < 8; i++) {
        int m = m0 + tm*8 + i;
        if (m >= BP) continue;
        float4 o0 = make_float4(acc[i][0], acc[i][1], acc[i][2], acc[i][3]);
        float4 o1 = make_float4(acc[i][4], acc[i][5], acc[i][6], acc[i][7]);
        *(float4*)&Cb[(long)m*128 + tn*8    ] = o0;
        *(float4*)&Cb[(long)m*128 + tn*8 + 4] = o1;
    }
}

// ---------------- bilinear reduce: out = sum partials + bias ------------------
__global__ void bl_reduce(const float* __restrict__ clsb, float* __restrict__ out)
{
    int m = blockIdx.x;
    int c = threadIdx.x;
    if (c >= NCc) return;
    float s = clsb[c];
    long o = (long)m*128 + c;
    #pragma unroll
    for (int kc = 0; kc < BLKS; kc++)
        s += g_blp[(long)kc*BP*128 + o];
    out[(long)m*NCc + c] = s;
}

// ---------------- launch ----------------
extern "C" void kernel_launch(void* const* d_in, const int* in_sizes, int n_in,
                              void* d_out, int out_size)
{
    const float* seq   = (const float*)d_in[0];
    const float* att   = (const float*)d_in[1];
    const float* headW = (const float*)d_in[2];
    const float* headb = (const float*)d_in[3];
    const float* tailW = (const float*)d_in[4];
    const float* tailb = (const float*)d_in[5];
    const float* projW = (const float*)d_in[6];
    const float* clsW  = (const float*)d_in[7];
    const float* clsb  = (const float*)d_in[8];
    const float* mmask = (const float*)d_in[9];
    const int*   midx  = (const int*)d_in[10];
    const int*   hts   = (const int*)d_in[11];
    float* out = (float*)d_out;

    float *p_ht, *p_rsp, *p_Wcp;
    cudaGetSymbolAddress((void**)&p_ht, g_ht);
    cudaGetSymbolAddress((void**)&p_rsp, g_rsp);
    cudaGetSymbolAddress((void**)&p_Wcp, g_Wcp);

    // Wc partials: cls_W @ proj_W, K-split 2
    {
        dim3 g(1, QQ/128, 2);
        gemm_nn128<<<g, 256>>>(clsW, projW, p_Wcp, NCc, QQ, Hh,
                               0, 0, (long)NCc*QQ, 2);
    }
    // merge + transpose -> g_WcT
    {
        dim3 g(QQ/32, 4), b(32, 8);
        wct_kernel<<<g, b>>>();
    }
    pool_kernel<<<Bb*NEe, 256>>>(seq, att, mmask, midx);
    htatt_kernel<<<Bb*Pp, 256>>>(hts);
    // E partials
    {
        dim3 g(2, Hh/64, 2*EKC);
        e_gemm<<<g, 256>>>(headW, tailW);
    }
    // rs partials: ht[b] @ seq[b], K-split 2 -> [kc][b][p][h]
    {
        dim3 g((Pp + 127)/128, Hh/128, Bb*2);
        gemm_nn128<<<g, 256>>>(p_ht, seq, p_rsp, Pp, Hh, Ls,
                               (long)Pp*Ls, (long)Ls*Hh, (long)Pp*Hh, 2);
    }
    // R[side] = (rsp0+rsp1) @ W2^T
    {
        dim3 g((BP + 127)/128, Hh/128, 2);
        r_gemm<<<g, 256>>>(headW, tailW);
    }
    // hs/ts = tanh(R + E[ent] + b)
    {
        dim3 g(BP, 2);
        fuse_tanh<<<g, 192>>>(headb, tailb, hts);
    }
    // bilinear partials + reduce
    {
        dim3 g((BP + 127)/128, 1, BLKS);
        bilinear_gemm<<<g, 256>>>();
        bl_reduce<<<BP, 128>>>(clsb, out);
    }
}

// round 7
// speedup vs baseline: 1.4473x; 1.4473x over previous
#include <cuda_runtime.h>
#include <math.h>

#define Bb   4
#define Ls   1024
#define Hh   768
#define NHh  12
#define NEe  30
#define Mm   6
#define Pp   600
#define EMBe 768
#define NCc  97
#define K2H  1536           // 2*H
#define QQ   12288          // EMB*BS
#define BP   (Bb*Pp)        // 2400
#define BE   (Bb*NEe)       // 120
#define EKC  3              // K-chunks for E gemm
#define BLKS 8              // bilinear K-split

// ---------------- scratch ----------------
__device__ float g_e_emb[BE*Hh];
__device__ float g_e_att[BE*NHh*Ls];
__device__ float g_ht  [BP*Ls];
__device__ float g_rs  [BP*Hh];
__device__ float g_R   [2*BP*Hh];          // [side][m][e]
__device__ float g_Ep  [EKC*2*BE*Hh];
__device__ float g_hs  [BP*EMBe];
__device__ float g_ts  [BP*EMBe];
__device__ float g_Wc  [NCc*QQ];
__device__ float g_WcT [QQ*128];           // transposed, c padded to 128
__device__ float g_blp [BP*BLKS*128];      // bilinear partials [m][kc][c]

// ---------------- kernel 1: entity pooling (vectorized) ----------------
__global__ void pool_kernel(const float* __restrict__ seq,
                            const float* __restrict__ att,
                            const float* __restrict__ mmask,
                            const int*   __restrict__ midx)
{
    int be = blockIdx.x;
    int b = be / NEe;
    __shared__ int   idx[Mm];
    __shared__ float msk[Mm];
    if (threadIdx.x < Mm) {
        idx[threadIdx.x] = midx[be*Mm + threadIdx.x];
        msk[threadIdx.x] = mmask[be*Mm + threadIdx.x];
    }
    __syncthreads();
    float cnt = 0.f;
    #pragma unroll
    for (int m = 0; m < Mm; m++) cnt += msk[m];
    cnt = fmaxf(cnt, 1.0f);
    float invc = 1.0f / cnt;

    for (int h = threadIdx.x; h < Hh; h += blockDim.x) {
        float v[Mm]; float mx = -1e30f;
        #pragma unroll
        for (int m = 0; m < Mm; m++) {
            float x = seq[((long)b*Ls + idx[m])*Hh + h];
            x = (msk[m] > 0.f) ? x : -1e30f;
            v[m] = x; mx = fmaxf(mx, x);
        }
        float s = 0.f;
        #pragma unroll
        for (int m = 0; m < Mm; m++) s += expf(v[m] - mx);
        g_e_emb[(long)be*Hh + h] = mx + logf(s);
    }
    for (int t = threadIdx.x; t < NHh*(Ls/4); t += blockDim.x) {
        int nh = t >> 8, lq = (t & 255)*4;
        float4 s4 = make_float4(0.f,0.f,0.f,0.f);
        #pragma unroll
        for (int m = 0; m < Mm; m++) {
            float4 a = *(const float4*)&att[(((long)b*NHh + nh)*Ls + idx[m])*Ls + lq];
            float w = msk[m];
            s4.x += a.x*w; s4.y += a.y*w; s4.z += a.z*w; s4.w += a.w*w;
        }
        s4.x *= invc; s4.y *= invc; s4.z *= invc; s4.w *= invc;
        *(float4*)&g_e_att[((long)be*NHh + nh)*Ls + lq] = s4;
    }
}

// ---------------- kernel 2: pairwise attention mix (float4) ----------------
__global__ void htatt_kernel(const int* __restrict__ hts)
{
    int bp = blockIdx.x;
    int b = bp / Pp;
    int he = hts[bp*2 + 0];
    int te = hts[bp*2 + 1];
    const float* ha = &g_e_att[((long)(b*NEe + he))*NHh*Ls];
    const float* ta = &g_e_att[((long)(b*NEe + te))*NHh*Ls];
    __shared__ float sv[Ls];
    __shared__ float red[256];
    int lq = threadIdx.x * 4;
    float4 s4 = make_float4(0.f,0.f,0.f,0.f);
    #pragma unroll
    for (int nh = 0; nh < NHh; nh++) {
        float4 a = *(const float4*)&ha[nh*Ls + lq];
        float4 t = *(const float4*)&ta[nh*Ls + lq];
        s4.x += a.x*t.x; s4.y += a.y*t.y; s4.z += a.z*t.z; s4.w += a.w*t.w;
    }
    const float inh = 1.0f / NHh;
    s4.x *= inh; s4.y *= inh; s4.z *= inh; s4.w *= inh;
    *(float4*)&sv[lq] = s4;
    red[threadIdx.x] = s4.x + s4.y + s4.z + s4.w;
    for (int o = 128; o > 0; o >>= 1) {
        __syncthreads();
        if (threadIdx.x < o) red[threadIdx.x] += red[threadIdx.x + o];
    }
    __syncthreads();
    float inv = 1.0f / (red[0] + 1e-30f);
    float4 v = *(const float4*)&sv[lq];
    v.x *= inv; v.y *= inv; v.z *= inv; v.w *= inv;
    *(float4*)&g_ht[(long)bp*Ls + lq] = v;
}

// ---------------- 128x128 NN GEMM, 8x8 micro, double-buffered (round-4) ------
__global__ __launch_bounds__(256,2) void gemm_nn128(
    const float* __restrict__ A, const float* __restrict__ B, float* __restrict__ C,
    int M, int N, int K, long sA, long sB, long sC)
{
    __shared__ float As[2][8][132];
    __shared__ float Bs[2][8][132];
    int bz = blockIdx.z;
    const float* Ab = A + (long)bz*sA;
    const float* Bp = B + (long)bz*sB;
    float*       Cb = C + (long)bz*sC;
    int m0 = blockIdx.x*128, n0 = blockIdx.y*128;
    int tid = threadIdx.x;

    int ar = tid >> 1, akq = (tid & 1)*4;
    int am = m0 + ar; if (am > M-1) am = M-1;
    int bkr = tid >> 5, bnq = (tid & 31)*4;
    const float* aptr = Ab + (long)am*K + akq;
    const float* bptr = Bp + (long)bkr*N + n0 + bnq;

    float4 av = *(const float4*)aptr;
    float4 bv = *(const float4*)bptr;

    int tm = tid & 15, tn = tid >> 4;
    float acc[8][8] = {};
    int buf = 0;
    As[0][akq+0][ar] = av.x; As[0][akq+1][ar] = av.y;
    As[0][akq+2][ar] = av.z; As[0][akq+3][ar] = av.w;
    *(float4*)&Bs[0][bkr][bnq] = bv;
    __syncthreads();

    for (int k0 = 0; k0 < K; k0 += 8) {
        bool next = (k0 + 8 < K);
        if (next) {
            aptr += 8; bptr += (long)8*N;
            av = *(const float4*)aptr;
            bv = *(const float4*)bptr;
        }
        #pragma unroll
        for (int kk = 0; kk < 8; kk++) {
            float a[8], b[8];
            *(float4*)&a[0] = *(const float4*)&As[buf][kk][tm*8];
            *(float4*)&a[4] = *(const float4*)&As[buf][kk][tm*8+4];
            *(float4*)&b[0] = *(const float4*)&Bs[buf][kk][tn*8];
            *(float4*)&b[4] = *(const float4*)&Bs[buf][kk][tn*8+4];
            #pragma unroll
            for (int i = 0; i < 8; i++)
                #pragma unroll
                for (int j = 0; j < 8; j++)
                    acc[i][j] += a[i]*b[j];
        }
        if (next) {
            int nb = buf ^ 1;
            As[nb][akq+0][ar] = av.x; As[nb][akq+1][ar] = av.y;
            As[nb][akq+2][ar] = av.z; As[nb][akq+3][ar] = av.w;
            *(float4*)&Bs[nb][bkr][bnq] = bv;
            __syncthreads();
            buf = nb;
        }
    }
    #pragma unroll
    for (int i = 0; i < 8; i++) {
        int m = m0 + tm*8 + i;
        if (m >= M) continue;
        float4 o0 = make_float4(acc[i][0], acc[i][1], acc[i][2], acc[i][3]);
        float4 o1 = make_float4(acc[i][4], acc[i][5], acc[i][6], acc[i][7]);
        *(float4*)&Cb[(long)m*N + n0 + tn*8    ] = o0;
        *(float4*)&Cb[(long)m*N + n0 + tn*8 + 4] = o1;
    }
}

// ---------------- Wc transpose: g_WcT[q][c] = g_Wc[c][q] ----------------
__global__ void wct_kernel()
{
    __shared__ float sm[32][33];
    int q0 = blockIdx.x * 32;
    int c0 = blockIdx.y * 32;
    int tx = threadIdx.x, ty = threadIdx.y;    // (32, 8)
    #pragma unroll
    for (int u = 0; u < 4; u++) {
        int c = c0 + ty + u*8;
        float v = 0.f;
        if (c < NCc) v = g_Wc[(long)c*QQ + q0 + tx];
        sm[ty + u*8][tx] = v;
    }
    __syncthreads();
    #pragma unroll
    for (int u = 0; u < 4; u++) {
        int q = q0 + ty + u*8;
        g_WcT[(long)q*128 + c0 + tx] = sm[tx][ty + u*8];
    }
}

// ---------------- R GEMM (NT): g_R[side] = g_rs @ W[:,768:]^T (round-4) ------
__global__ __launch_bounds__(256,2) void r_gemm(
    const float* __restrict__ headW, const float* __restrict__ tailW)
{
    __shared__ float As[2][8][132];
    __shared__ float Bs[2][8][132];
    int side = blockIdx.z;
    const float* W = side ? tailW : headW;
    float* Cb = g_R + (long)side*BP*Hh;
    int m0 = blockIdx.x*128, n0 = blockIdx.y*128;
    int tid = threadIdx.x;

    int ar = tid >> 1, akq = (tid & 1)*4;
    int am = m0 + ar; if (am > BP-1) am = BP-1;
    int bn = tid >> 1, bkq = (tid & 1)*4;
    const float* aptr = g_rs + (long)am*Hh + akq;
    const float* bptr = W + (long)(n0 + bn)*K2H + Hh + bkq;

    float4 av = *(const float4*)aptr;
    float4 bv = *(const float4*)bptr;

    int tm = tid & 15, tn = tid >> 4;
    float acc[8][8] = {};
    int buf = 0;
    As[0][akq+0][ar] = av.x; As[0][akq+1][ar] = av.y;
    As[0][akq+2][ar] = av.z; As[0][akq+3][ar] = av.w;
    Bs[0][bkq+0][bn] = bv.x; Bs[0][bkq+1][bn] = bv.y;
    Bs[0][bkq+2][bn] = bv.z; Bs[0][bkq+3][bn] = bv.w;
    __syncthreads();

    for (int k0 = 0; k0 < Hh; k0 += 8) {
        bool next = (k0 + 8 < Hh);
        if (next) {
            aptr += 8; bptr += 8;
            av = *(const float4*)aptr;
            bv = *(const float4*)bptr;
        }
        #pragma unroll
        for (int kk = 0; kk < 8; kk++) {
            float a[8], b[8];
            *(float4*)&a[0] = *(const float4*)&As[buf][kk][tm*8];
            *(float4*)&a[4] = *(const float4*)&As[buf][kk][tm*8+4];
            *(float4*)&b[0] = *(const float4*)&Bs[buf][kk][tn*8];
            *(float4*)&b[4] = *(const float4*)&Bs[buf][kk][tn*8+4];
            #pragma unroll
            for (int i = 0; i < 8; i++)
                #pragma unroll
                for (int j = 0; j < 8; j++)
                    acc[i][j] += a[i]*b[j];
        }
        if (next) {
            int nb = buf ^ 1;
            As[nb][akq+0][ar] = av.x; As[nb][akq+1][ar] = av.y;
            As[nb][akq+2][ar] = av.z; As[nb][akq+3][ar] = av.w;
            Bs[nb][bkq+0][bn] = bv.x; Bs[nb][bkq+1][bn] = bv.y;
            Bs[nb][bkq+2][bn] = bv.z; Bs[nb][bkq+3][bn] = bv.w;
            __syncthreads();
            buf = nb;
        }
    }
    #pragma unroll
    for (int i = 0; i < 8; i++) {
        int m = m0 + tm*8 + i;
        if (m >= BP) continue;
        float4 o0 = make_float4(acc[i][0], acc[i][1], acc[i][2], acc[i][3]);
        float4 o1 = make_float4(acc[i][4], acc[i][5], acc[i][6], acc[i][7]);
        *(float4*)&Cb[(long)m*Hh + n0 + tn*8    ] = o0;
        *(float4*)&Cb[(long)m*Hh + n0 + tn*8 + 4] = o1;
    }
}

// ---------------- E GEMM (NT, K-chunked, 64x64 tile) ----------------
__global__ __launch_bounds__(256) void e_gemm(
    const float* __restrict__ headW, const float* __restrict__ tailW)
{
    __shared__ float As[16][65];
    __shared__ float Bs[16][65];
    int z = blockIdx.z;
    int side = z & 1, kc = z >> 1;
    const float* W = side ? tailW : headW;
    float* Cb = g_Ep + (long)(kc*2 + side)*BE*Hh;
    int m0 = blockIdx.x*64, n0 = blockIdx.y*64;
    int tid = threadIdx.x;
    int tm = tid & 15, tn = tid >> 4;
    float acc[4][4] = {};
    int kbeg = kc*256, kend = kbeg + 256;
    for (int k0 = kbeg; k0 < kend; k0 += 16) {
        #pragma unroll
        for (int i = 0; i < 4; i++) {
            int idx = tid + i*256;
            int m = idx >> 4, k = idx & 15;
            int mg = m0 + m; if (mg > BE-1) mg = BE-1;
            As[k][m] = g_e_emb[(long)mg*Hh + k0 + k];
        }
        #pragma unroll
        for (int i = 0; i < 4; i++) {
            int idx = tid + i*256;
            int e = idx >> 4, k = idx & 15;
            Bs[k][e] = W[(long)(n0 + e)*K2H + k0 + k];
        }
        __syncthreads();
        #pragma unroll
        for (int kk = 0; kk < 16; kk++) {
            float a[4], bb[4];
            #pragma unroll
            for (int i = 0; i < 4; i++) a[i]  = As[kk][tm + 16*i];
            #pragma unroll
            for (int j = 0; j < 4; j++) bb[j] = Bs[kk][tn + 16*j];
            #pragma unroll
            for (int i = 0; i < 4; i++)
                #pragma unroll
                for (int j = 0; j < 4; j++)
                    acc[i][j] += a[i]*bb[j];
        }
        __syncthreads();
    }
    #pragma unroll
    for (int i = 0; i < 4; i++) {
        int m = m0 + tm + 16*i;
        if (m >= BE) continue;
        #pragma unroll
        for (int j = 0; j < 4; j++)
            Cb[(long)m*Hh + n0 + tn + 16*j] = acc[i][j];
    }
}

// ---------------- fused gather + add + tanh ----------------
__global__ void fuse_tanh(const float* __restrict__ headb,
                          const float* __restrict__ tailb,
                          const int*   __restrict__ hts)
{
    int m = blockIdx.x, side = blockIdx.y;
    int b = m / Pp;
    int ent = hts[m*2 + side];
    int er = b*NEe + ent;
    const float* Rr   = g_R + ((long)side*BP + m)*Hh;
    const float* bias = side ? tailb : headb;
    float* outp = (side ? g_ts : g_hs) + (long)m*EMBe;
    const float* e0 = g_Ep + (long)(0*2 + side)*BE*Hh + (long)er*Hh;
    const float* e1 = g_Ep + (long)(1*2 + side)*BE*Hh + (long)er*Hh;
    const float* e2 = g_Ep + (long)(2*2 + side)*BE*Hh + (long)er*Hh;
    int e = threadIdx.x * 4;
    float4 r  = *(const float4*)&Rr[e];
    float4 p0 = *(const float4*)&e0[e];
    float4 p1 = *(const float4*)&e1[e];
    float4 p2 = *(const float4*)&e2[e];
    float4 bi = *(const float4*)&bias[e];
    float4 o;
    o.x = tanhf(r.x + p0.x + p1.x + p2.x + bi.x);
    o.y = tanhf(r.y + p0.y + p1.y + p2.y + bi.y);
    o.z = tanhf(r.z + p0.z + p1.z + p2.z + bi.z);
    o.w = tanhf(r.w + p0.w + p1.w + p2.w + bi.w);
    *(float4*)&outp[e] = o;
}

// ---------------- bilinear as GEMM: A materialized, B = WcT -------------------
// A[m,q] = hs[m,16kb+i]*ts[m,16kb+j], q = 256kb+16i+j.  N = 128 (c padded).
// grid (19, 1, BLKS); k-range per block = QQ/BLKS = 1536.
// NOTE: no min-blocks clause — avoid forced 128-reg cap (spill risk in hot loop).
__global__ __launch_bounds__(256) void bilinear_gemm()
{
    __shared__ float As[2][8][132];
    __shared__ float Bs[2][8][132];
    int kc = blockIdx.z;
    int kbeg = kc * (QQ / BLKS), kend = kbeg + (QQ / BLKS);
    int m0 = blockIdx.x*128;
    int tid = threadIdx.x;

    int ar = tid >> 1, akq = (tid & 1)*4;
    int am = m0 + ar; if (am > BP-1) am = BP-1;
    int bkr = tid >> 5, bnq = (tid & 31)*4;
    const float* bptr = g_WcT + (long)(kbeg + bkr)*128 + bnq;
    const float* hrow = g_hs + (long)am*EMBe;
    const float* trow = g_ts + (long)am*EMBe;

    int kb = kbeg >> 8, iQ = (kbeg >> 4) & 15, jb = kbeg & 8;
    float4 t4 = *(const float4*)&trow[(kb<<4) + jb + akq];
    float  hv = hrow[(kb<<4) + iQ];
    float4 av = make_float4(hv*t4.x, hv*t4.y, hv*t4.z, hv*t4.w);
    float4 bv = *(const float4*)bptr;

    int tm = tid & 15, tn = tid >> 4;
    float acc[8][8] = {};
    int buf = 0;
    As[0][akq+0][ar] = av.x; As[0][akq+1][ar] = av.y;
    As[0][akq+2][ar] = av.z; As[0][akq+3][ar] = av.w;
    *(float4*)&Bs[0][bkr][bnq] = bv;
    __syncthreads();

    for (int k0 = kbeg; k0 < kend; k0 += 8) {
        bool next = (k0 + 8 < kend);
        if (next) {
            int q1 = k0 + 8;
            kb = q1 >> 8; iQ = (q1 >> 4) & 15; jb = q1 & 8;
            t4 = *(const float4*)&trow[(kb<<4) + jb + akq];
            hv = hrow[(kb<<4) + iQ];
            av = make_float4(hv*t4.x, hv*t4.y, hv*t4.z, hv*t4.w);
            bptr += 8*128;
            bv = *(const float4*)bptr;
        }
        #pragma unroll
        for (int kk = 0; kk < 8; kk++) {
            float a[8], b[8];
            *(float4*)&a[0] = *(const float4*)&As[buf][kk][tm*8];
            *(float4*)&a[4] = *(const float4*)&As[buf][kk][tm*8+4];
            *(float4*)&b[0] = *(const float4*)&Bs[buf][kk][tn*8];
            *(float4*)&b[4] = *(const float4*)&Bs[buf][kk][tn*8+4];
            #pragma unroll
            for (int i = 0; i < 8; i++)
                #pragma unroll
                for (int j = 0; j < 8; j++)
                    acc[i][j] += a[i]*b[j];
        }
        if (next) {
            int nb = buf ^ 1;
            As[nb][akq+0][ar] = av.x; As[nb][akq+1][ar] = av.y;
            As[nb][akq+2][ar] = av.z; As[nb][akq+3][ar] = av.w;
            *(float4*)&Bs[nb][bkr][bnq] = bv;
            __syncthreads();
            buf = nb;
        }
    }
    // partial layout [m][kc][c]
    #pragma unroll
    for (int i = 0; i < 8; i++) {
        int m = m0 + tm*8 + i;
        if (m >= BP) continue;
        float* row = g_blp + ((long)m*BLKS + kc)*128;
        float4 o0 = make_float4(acc[i][0], acc[i][1], acc[i][2], acc[i][3]);
        float4 o1 = make_float4(acc[i][4], acc[i][5], acc[i][6], acc[i][7]);
        *(float4*)&row[tn*8    ] = o0;
        *(float4*)&row[tn*8 + 4] = o1;
    }
}

// ---------------- bilinear reduce: out = sum partials + bias ------------------
__global__ void bl_reduce(const float* __restrict__ clsb, float* __restrict__ out)
{
    int m = blockIdx.x;
    int c = threadIdx.x;
    if (c >= NCc) return;
    float s = clsb[c];
    const float* base = g_blp + (long)m*BLKS*128 + c;
    #pragma unroll
    for (int kc = 0; kc < BLKS; kc++)
        s += base[kc*128];
    out[(long)m*NCc + c] = s;
}

// ---------------- launch ----------------
extern "C" void kernel_launch(void* const* d_in, const int* in_sizes, int n_in,
                              void* d_out, int out_size)
{
    const float* seq   = (const float*)d_in[0];
    const float* att   = (const float*)d_in[1];
    const float* headW = (const float*)d_in[2];
    const float* headb = (const float*)d_in[3];
    const float* tailW = (const float*)d_in[4];
    const float* tailb = (const float*)d_in[5];
    const float* projW = (const float*)d_in[6];
    const float* clsW  = (const float*)d_in[7];
    const float* clsb  = (const float*)d_in[8];
    const float* mmask = (const float*)d_in[9];
    const int*   midx  = (const int*)d_in[10];
    const int*   hts   = (const int*)d_in[11];
    float* out = (float*)d_out;

    float *p_ht, *p_rs, *p_Wc;
    cudaGetSymbolAddress((void**)&p_ht, g_ht);
    cudaGetSymbolAddress((void**)&p_rs, g_rs);
    cudaGetSymbolAddress((void**)&p_Wc, g_Wc);

    // Wc = cls_W @ proj_W   [97,768]@[768,12288]
    {
        dim3 g(1, QQ/128, 1);
        gemm_nn128<<<g, 256>>>(clsW, projW, p_Wc, NCc, QQ, Hh, 0, 0, 0);
    }
    // transpose -> g_WcT
    {
        dim3 g(QQ/32, 4), b(32, 8);
        wct_kernel<<<g, b>>>();
    }
    pool_kernel<<<Bb*NEe, 256>>>(seq, att, mmask, midx);
    htatt_kernel<<<Bb*Pp, 256>>>(hts);
    // E partials
    {
        dim3 g(2, Hh/64, 2*EKC);
        e_gemm<<<g, 256>>>(headW, tailW);
    }
    // rs[b] = ht[b] @ seq[b]
    {
        dim3 g((Pp + 127)/128, Hh/128, Bb);
        gemm_nn128<<<g, 256>>>(p_ht, seq, p_rs, Pp, Hh, Ls,
                               (long)Pp*Ls, (long)Ls*Hh, (long)Pp*Hh);
    }
    // R[side] = rs @ W2^T
    {
        dim3 g((BP + 127)/128, Hh/128, 2);
        r_gemm<<<g, 256>>>(headW, tailW);
    }
    // hs/ts = tanh(R + E[ent] + b)
    {
        dim3 g(BP, 2);
        fuse_tanh<<<g, 192>>>(headb, tailb, hts);
    }
    // bilinear partials + reduce
    {
        dim3 g((BP + 127)/128, 1, BLKS);
        bilinear_gemm<<<g, 256>>>();
        bl_reduce<<<BP, 128>>>(clsb, out);
    }
}